// round 1
// baseline (speedup 1.0000x reference)
#include <cuda_runtime.h>
#include <math.h>
#include <stdint.h>

// Problem constants
#define BB 4
#define BN 512
#define DD 64
#define HH 8
#define BH (BB*HH)        // 32
#define NROWS (BB*BN)     // 2048

// ---------------- scratch (static device globals; no allocs) ----------------
__device__ float g_Q [NROWS*DD];
__device__ float g_K [NROWS*DD];   // pre-scaled by DH^-0.5
__device__ float g_V [NROWS*DD];
__device__ float g_Q2[NROWS*DD];
__device__ float g_K2[NROWS*DD];   // pre-scaled
__device__ float g_scores[(size_t)BH*BN*BN];  // 33.5 MB
__device__ unsigned g_maxbits[BH];
__device__ float g_hatt[NROWS*DD];

// ---------------- K0: init max accumulators ----------------
__global__ void k0_init() {
    if (threadIdx.x < BH) g_maxbits[threadIdx.x] = 0u;  // key-space -inf
}

// ---------------- K1: x = LN(h+p); Q,K,V,Q2,K2 projections ----------------
__global__ void __launch_bounds__(64) k1_proj(
    const float* __restrict__ h, const float* __restrict__ p,
    const float* __restrict__ g1, const float* __restrict__ b1,
    const float* __restrict__ WQ, const float* __restrict__ WK,
    const float* __restrict__ WV, const float* __restrict__ WQ2,
    const float* __restrict__ WK2)
{
    int row = blockIdx.x;
    int t = threadIdx.x;
    __shared__ float xs[64];
    __shared__ float red[4];

    float v = h[row*64 + t] + p[row*64 + t];
    float s = v, sq = v*v;
    #pragma unroll
    for (int off = 16; off; off >>= 1) {
        s  += __shfl_down_sync(0xffffffffu, s,  off);
        sq += __shfl_down_sync(0xffffffffu, sq, off);
    }
    int wid = t >> 5, lane = t & 31;
    if (lane == 0) { red[wid*2] = s; red[wid*2+1] = sq; }
    __syncthreads();
    float S  = red[0] + red[2];
    float SQ = red[1] + red[3];
    float mean = S * (1.f/64.f);
    float var  = SQ * (1.f/64.f) - mean*mean;
    float rinv = 1.f / sqrtf(var + 1e-5f);
    xs[t] = (v - mean) * rinv * g1[t] + b1[t];
    __syncthreads();

    float q = 0.f, k = 0.f, vv = 0.f, q2 = 0.f, k2 = 0.f;
    #pragma unroll 8
    for (int d = 0; d < 64; ++d) {
        float x = xs[d];
        q  += x * WQ [d*64 + t];
        k  += x * WK [d*64 + t];
        vv += x * WV [d*64 + t];
        q2 += x * WQ2[d*64 + t];
        k2 += x * WK2[d*64 + t];
    }
    const float sc = 0.35355339059327373f;  // 8^-0.5
    g_Q [row*64 + t] = q;
    g_K [row*64 + t] = k * sc;
    g_V [row*64 + t] = vv;
    g_Q2[row*64 + t] = q2;
    g_K2[row*64 + t] = k2 * sc;
}

// ---------------- K2: fused scores (dense E2 path + sparse adj E path) ------
// Block = one (b,i). 128 threads. Per 64-j tile:
//   dense: score2[h,j] = sum_k K2[j,hk] * (e_j . A2_i[:,hk]),  A2_i = W_E2 * Q2_i
//   sparse (adj set): score1 via W_E,Q,K cooperative matvec, overwrites entry
__global__ void __launch_bounds__(128) k2_scores(
    const float* __restrict__ e, const unsigned* __restrict__ adj,
    const float* __restrict__ WE, const float* __restrict__ WE2)
{
    int bi = blockIdx.x;
    int b = bi >> 9, i = bi & 511;
    __shared__ float es [64][68];   // e tile, transposed: es[d][j_local]
    __shared__ float A2s[64][68];
    __shared__ float qs[64], q2s[64];
    __shared__ int lst[64];
    __shared__ int cnt;
    __shared__ unsigned char adjf[64];
    int t = threadIdx.x;

    if (t < 64) qs[t] = g_Q[bi*64 + t];
    else        q2s[t-64] = g_Q2[bi*64 + (t-64)];
    __syncthreads();
    for (int idx = t; idx < 4096; idx += 128)
        A2s[idx >> 6][idx & 63] = WE2[idx] * q2s[idx & 63];

    int h = t >> 4, i16 = t & 15;
    const float* ebase = e + (size_t)bi * BN * 64;
    const size_t srow = ((size_t)(b*8 + h) * BN + i) * BN;

    for (int jt = 0; jt < 8; ++jt) {
        int j0 = jt * 64;
        __syncthreads();               // prior tile fully consumed (also covers A2s build)
        if (t == 0) cnt = 0;
        for (int idx = t; idx < 4096; idx += 128) {
            int jl = idx >> 6, d = idx & 63;
            es[d][jl] = ebase[(size_t)(j0 + jl)*64 + d];
        }
        __syncthreads();               // es ready, cnt reset visible
        if (t < 64) {
            unsigned a = adj[(size_t)bi * BN + j0 + t];
            adjf[t] = a ? 1 : 0;
            if (a) { int pos = atomicAdd(&cnt, 1); lst[pos] = t; }
        }
        __syncthreads();               // list/flags ready

        // ---- dense E2 path: thread owns (h, 4 consecutive j) ----
        float acc[32];
        #pragma unroll
        for (int z = 0; z < 32; ++z) acc[z] = 0.f;
        #pragma unroll 4
        for (int d = 0; d < 64; ++d) {
            float4 ev = *(const float4*)&es[d][i16*4];
            float4 a0 = *(const float4*)&A2s[d][h*8];
            float4 a1 = *(const float4*)&A2s[d][h*8 + 4];
            float evv[4] = {ev.x, ev.y, ev.z, ev.w};
            float av [8] = {a0.x, a0.y, a0.z, a0.w, a1.x, a1.y, a1.z, a1.w};
            #pragma unroll
            for (int jj = 0; jj < 4; ++jj)
                #pragma unroll
                for (int k = 0; k < 8; ++k)
                    acc[jj*8 + k] += evv[jj] * av[k];
        }
        #pragma unroll
        for (int jj = 0; jj < 4; ++jj) {
            int jl = i16*4 + jj;
            if (!adjf[jl]) {
                int j = j0 + jl;
                const float4* kp = (const float4*)&g_K2[((size_t)(b*BN + j))*64 + h*8];
                float4 k0 = kp[0], k1 = kp[1];
                float sv = acc[jj*8+0]*k0.x + acc[jj*8+1]*k0.y
                         + acc[jj*8+2]*k0.z + acc[jj*8+3]*k0.w
                         + acc[jj*8+4]*k1.x + acc[jj*8+5]*k1.y
                         + acc[jj*8+6]*k1.z + acc[jj*8+7]*k1.w;
                g_scores[srow + j] = sv;
            }
        }

        // ---- sparse E path for adj-set columns (cooperative, warps 0-1) ----
        int n = cnt;
        for (int q = 0; q < n; ++q) {
            int jl = lst[q];
            if (t < 64) {
                float y = 0.f;
                #pragma unroll 8
                for (int d = 0; d < 64; ++d) y += es[d][jl] * WE[d*64 + t];
                y *= qs[t];
                int j = j0 + jl;
                float z = y * g_K[((size_t)(b*BN + j))*64 + t];
                z += __shfl_xor_sync(0xffffffffu, z, 4);
                z += __shfl_xor_sync(0xffffffffu, z, 2);
                z += __shfl_xor_sync(0xffffffffu, z, 1);
                if ((t & 7) == 0)
                    g_scores[((size_t)(b*8 + (t >> 3)) * BN + i) * BN + j] = z;
            }
        }
    }
}

// ---------------- K3: global max per (b,h) ----------------
__device__ __forceinline__ unsigned f2key(float f) {
    unsigned u = __float_as_uint(f);
    return (u & 0x80000000u) ? ~u : (u | 0x80000000u);
}
__device__ __forceinline__ float key2f(unsigned key) {
    unsigned u = (key & 0x80000000u) ? (key ^ 0x80000000u) : ~key;
    return __uint_as_float(u);
}
__global__ void __launch_bounds__(256) k3_max() {
    int bh = blockIdx.x >> 3, ch = blockIdx.x & 7;
    const float* base = g_scores + (size_t)bh*BN*BN + (size_t)ch*32768;
    float m = -INFINITY;
    for (int idx = threadIdx.x; idx < 32768; idx += 256) m = fmaxf(m, base[idx]);
    #pragma unroll
    for (int off = 16; off; off >>= 1) m = fmaxf(m, __shfl_xor_sync(0xffffffffu, m, off));
    __shared__ float red[8];
    if ((threadIdx.x & 31) == 0) red[threadIdx.x >> 5] = m;
    __syncthreads();
    if (threadIdx.x < 8) {
        float mm = red[threadIdx.x];
        mm = fmaxf(mm, __shfl_xor_sync(0x000000ffu, mm, 4));
        mm = fmaxf(mm, __shfl_xor_sync(0x000000ffu, mm, 2));
        mm = fmaxf(mm, __shfl_xor_sync(0x000000ffu, mm, 1));
        if (threadIdx.x == 0) atomicMax(&g_maxbits[bh], f2key(mm));
    }
}

// ---------------- K4: exp/mask/k_RW + rowsum + att@V ----------------
// Block = (b, 8 i-rows, all h). 8 warps = 8 heads. V staged transposed in smem.
__global__ void __launch_bounds__(256) k4_att(
    const float* __restrict__ kRW, const float* __restrict__ mask)
{
    extern __shared__ float Vs[];  // [64][513] : Vs[c*513 + j]
    int b  = blockIdx.y;
    int i0 = blockIdx.x * 8;
    int t = threadIdx.x, lane = t & 31, h = t >> 5;

    for (int idx = t; idx < BN*64; idx += 256) {
        int j = idx >> 6, c = idx & 63;
        Vs[c*513 + j] = g_V[((size_t)(b*BN + j))*64 + c];
    }
    __syncthreads();

    float mx = key2f(g_maxbits[b*8 + h]);

    for (int ii = 0; ii < 8; ++ii) {
        int i = i0 + ii;
        float mi = mask[b*BN + i];
        const float* sp = g_scores + ((size_t)(b*8 + h)*BN + i)*BN;
        const float* wp = kRW + ((size_t)(b*BN + i))*BN;
        float pden = 0.f;
        float pav[8];
        #pragma unroll
        for (int k = 0; k < 8; ++k) pav[k] = 0.f;

        for (int jt = 0; jt < 16; ++jt) {
            int j = jt*32 + lane;
            float pw = expf(sp[j] - mx) * wp[j] * mask[b*BN + j] * mi;
            pden += pw;
            #pragma unroll
            for (int k = 0; k < 8; ++k) pav[k] += pw * Vs[(h*8 + k)*513 + j];
        }
        #pragma unroll
        for (int off = 16; off; off >>= 1) {
            pden += __shfl_down_sync(0xffffffffu, pden, off);
            #pragma unroll
            for (int k = 0; k < 8; ++k) pav[k] += __shfl_down_sync(0xffffffffu, pav[k], off);
        }
        if (lane == 0) {
            float inv = 1.f / fmaxf(pden, 1e-6f);
            float4* op = (float4*)&g_hatt[((size_t)(b*BN + i))*64 + h*8];
            op[0] = make_float4(pav[0]*inv, pav[1]*inv, pav[2]*inv, pav[3]*inv);
            op[1] = make_float4(pav[4]*inv, pav[5]*inv, pav[6]*inv, pav[7]*inv);
        }
    }
}

// ---------------- K5: O-proj + residual + LN2 + FFN + residual ----------------
__global__ void __launch_bounds__(64) k5_out(
    const float* __restrict__ hin, const float* __restrict__ OW,
    const float* __restrict__ Ob, const float* __restrict__ g2,
    const float* __restrict__ b2, const float* __restrict__ Wf1,
    const float* __restrict__ bf1, const float* __restrict__ Wf2,
    const float* __restrict__ bf2, float* __restrict__ out)
{
    int row = blockIdx.x;
    int t = threadIdx.x;
    __shared__ float has[64], ys[64], hid[128];
    __shared__ float red[4];

    has[t] = g_hatt[row*64 + t];
    __syncthreads();

    float a = hin[row*64 + t] + Ob[t];
    #pragma unroll 8
    for (int d = 0; d < 64; ++d) a += has[d] * OW[d*64 + t];
    // a == h2[row, t]

    float s = a, sq = a*a;
    #pragma unroll
    for (int off = 16; off; off >>= 1) {
        s  += __shfl_down_sync(0xffffffffu, s,  off);
        sq += __shfl_down_sync(0xffffffffu, sq, off);
    }
    int wid = t >> 5, lane = t & 31;
    if (lane == 0) { red[wid*2] = s; red[wid*2+1] = sq; }
    __syncthreads();
    float S  = red[0] + red[2];
    float SQ = red[1] + red[3];
    float mean = S * (1.f/64.f);
    float var  = SQ * (1.f/64.f) - mean*mean;
    float rinv = 1.f / sqrtf(var + 1e-5f);
    ys[t] = (a - mean) * rinv * g2[t] + b2[t];
    __syncthreads();

    float h0 = bf1[t], h1 = bf1[t + 64];
    #pragma unroll 8
    for (int d = 0; d < 64; ++d) {
        float x = ys[d];
        h0 += x * Wf1[d*128 + t];
        h1 += x * Wf1[d*128 + t + 64];
    }
    hid[t]      = fmaxf(h0, 0.f);
    hid[t + 64] = fmaxf(h1, 0.f);
    __syncthreads();

    float o = a + bf2[t];
    #pragma unroll 8
    for (int c = 0; c < 128; ++c) o += hid[c] * Wf2[c*64 + t];
    out[row*64 + t] = o;
}

// ---------------- launch ----------------
extern "C" void kernel_launch(void* const* d_in, const int* in_sizes, int n_in,
                              void* d_out, int out_size)
{
    const float* h    = (const float*)d_in[0];
    const float* p    = (const float*)d_in[1];
    const float* e    = (const float*)d_in[2];
    const float* kRW  = (const float*)d_in[3];
    const float* mask = (const float*)d_in[4];
    const unsigned* adj = (const unsigned*)d_in[5];
    const float* WQ   = (const float*)d_in[6];
    const float* WK   = (const float*)d_in[7];
    const float* WV   = (const float*)d_in[8];
    const float* WQ2  = (const float*)d_in[9];
    const float* WK2  = (const float*)d_in[10];
    const float* WE   = (const float*)d_in[11];
    const float* WE2  = (const float*)d_in[12];
    const float* OW   = (const float*)d_in[13];
    const float* Ob   = (const float*)d_in[14];
    const float* g1   = (const float*)d_in[15];
    const float* b1   = (const float*)d_in[16];
    const float* g2   = (const float*)d_in[17];
    const float* b2   = (const float*)d_in[18];
    const float* Wf1  = (const float*)d_in[19];
    const float* bf1  = (const float*)d_in[20];
    const float* Wf2  = (const float*)d_in[21];
    const float* bf2  = (const float*)d_in[22];
    float* out = (float*)d_out;

    cudaFuncSetAttribute(k4_att, cudaFuncAttributeMaxDynamicSharedMemorySize, 64*513*4);

    k0_init<<<1, 32>>>();
    k1_proj<<<NROWS, 64>>>(h, p, g1, b1, WQ, WK, WV, WQ2, WK2);
    k2_scores<<<NROWS, 128>>>(e, adj, WE, WE2);
    k3_max<<<BH*8, 256>>>();
    k4_att<<<dim3(64, BB), 256, 64*513*4>>>(kRW, mask);
    k5_out<<<NROWS, 64>>>(h, OW, Ob, g2, b2, Wf1, bf1, Wf2, bf2, out);
}

// round 2
// speedup vs baseline: 1.3760x; 1.3760x over previous
#include <cuda_runtime.h>
#include <math.h>
#include <stdint.h>

// Problem constants
#define BB 4
#define BN 512
#define DD 64
#define HH 8
#define BH (BB*HH)        // 32
#define NROWS (BB*BN)     // 2048

// ---------------- scratch (static device globals; no allocs) ----------------
__device__ float g_Q [NROWS*DD];
__device__ float g_K [NROWS*DD];   // pre-scaled by DH^-0.5
__device__ float g_V [NROWS*DD];
__device__ float g_Q2[NROWS*DD];
__device__ float g_K2[NROWS*DD];   // pre-scaled
__device__ float g_scores[(size_t)BH*BN*BN];  // 33.5 MB
__device__ unsigned g_maxbits[BH];
__device__ float g_hatt[NROWS*DD];

// ---------------- helpers ----------------
__device__ __forceinline__ uint32_t f2tf32(float f) {
    uint32_t r;
    asm("cvt.rna.tf32.f32 %0, %1;" : "=r"(r) : "f"(f));
    return r;
}
__device__ __forceinline__ void mma_tf32(float c[4],
    uint32_t a0, uint32_t a1, uint32_t a2, uint32_t a3,
    uint32_t b0, uint32_t b1)
{
    asm volatile(
        "mma.sync.aligned.m16n8k8.row.col.f32.tf32.tf32.f32 "
        "{%0,%1,%2,%3}, {%4,%5,%6,%7}, {%8,%9}, {%0,%1,%2,%3};"
        : "+f"(c[0]), "+f"(c[1]), "+f"(c[2]), "+f"(c[3])
        : "r"(a0), "r"(a1), "r"(a2), "r"(a3), "r"(b0), "r"(b1));
}

// ---------------- K0: init max accumulators ----------------
__global__ void k0_init() {
    if (threadIdx.x < BH) g_maxbits[threadIdx.x] = 0u;  // key-space -inf
}

// ---------------- K1: x = LN(h+p); Q,K,V,Q2,K2 projections ----------------
__global__ void __launch_bounds__(64) k1_proj(
    const float* __restrict__ h, const float* __restrict__ p,
    const float* __restrict__ g1, const float* __restrict__ b1,
    const float* __restrict__ WQ, const float* __restrict__ WK,
    const float* __restrict__ WV, const float* __restrict__ WQ2,
    const float* __restrict__ WK2)
{
    int row = blockIdx.x;
    int t = threadIdx.x;
    __shared__ float xs[64];
    __shared__ float red[4];

    float v = h[row*64 + t] + p[row*64 + t];
    float s = v, sq = v*v;
    #pragma unroll
    for (int off = 16; off; off >>= 1) {
        s  += __shfl_down_sync(0xffffffffu, s,  off);
        sq += __shfl_down_sync(0xffffffffu, sq, off);
    }
    int wid = t >> 5, lane = t & 31;
    if (lane == 0) { red[wid*2] = s; red[wid*2+1] = sq; }
    __syncthreads();
    float S  = red[0] + red[2];
    float SQ = red[1] + red[3];
    float mean = S * (1.f/64.f);
    float var  = SQ * (1.f/64.f) - mean*mean;
    float rinv = 1.f / sqrtf(var + 1e-5f);
    xs[t] = (v - mean) * rinv * g1[t] + b1[t];
    __syncthreads();

    float q = 0.f, k = 0.f, vv = 0.f, q2 = 0.f, k2 = 0.f;
    #pragma unroll 8
    for (int d = 0; d < 64; ++d) {
        float x = xs[d];
        q  += x * WQ [d*64 + t];
        k  += x * WK [d*64 + t];
        vv += x * WV [d*64 + t];
        q2 += x * WQ2[d*64 + t];
        k2 += x * WK2[d*64 + t];
    }
    const float sc = 0.35355339059327373f;  // 8^-0.5
    g_Q [row*64 + t] = q;
    g_K [row*64 + t] = k * sc;
    g_V [row*64 + t] = vv;
    g_Q2[row*64 + t] = q2;
    g_K2[row*64 + t] = k2 * sc;
}

// ---------------- K2: tensor-core fused scores ----------------
// Block = one (b,i), 128 threads = 4 warps.
// Dense: Y = e_tile[64x64] @ A2_i[64x64] via tf32 mma, then per-row 8-dot with K2.
// Sparse (adj set): cooperative Q*K*E matvec, one column per warp.
#define SMS 72   // padded smem row stride (bank-conflict-free)
__global__ void __launch_bounds__(128) k2_scores(
    const float* __restrict__ e, const unsigned* __restrict__ adj,
    const float* __restrict__ WE, const float* __restrict__ WE2)
{
    extern __shared__ uint32_t dyn[];
    uint32_t* es  = dyn;                 // [64][SMS] tf32 bits, row=j, col=d
    uint32_t* A2s = dyn + 64*SMS;        // [64][SMS] tf32 bits, row=d, col=hk
    float*    K2s = (float*)(dyn + 2*64*SMS);  // [64][SMS] fp32, row=j, col=hk

    __shared__ float qs[64], q2s[64];
    __shared__ int lst[64];
    __shared__ int cnt;
    __shared__ unsigned char adjf[64];

    int bi = blockIdx.x;
    int b = bi >> 9, i = bi & 511;
    int t = threadIdx.x;
    int w = t >> 5, lane = t & 31;
    int r = lane >> 2, cq = lane & 3;
    int m_base = w * 16;

    if (t < 64) qs[t] = g_Q[bi*64 + t];
    else        q2s[t-64] = g_Q2[bi*64 + (t-64)];
    __syncthreads();
    for (int idx = t; idx < 4096; idx += 128) {
        int d = idx >> 6, hk = idx & 63;
        A2s[d*SMS + hk] = f2tf32(WE2[idx] * q2s[hk]);
    }

    const float4* ebase  = (const float4*)(e + (size_t)bi * BN * 64);
    const float4* k2base = (const float4*)(g_K2 + (size_t)b * BN * 64);

    for (int jt = 0; jt < 8; ++jt) {
        int j0 = jt * 64;
        __syncthreads();       // prior tile fully consumed (also covers A2s build)
        if (t == 0) cnt = 0;
        // stage e tile (cvt to tf32) and K2 tile
        for (int idx = t; idx < 1024; idx += 128) {
            int jl = idx >> 4, c4 = idx & 15;
            float4 v = ebase[(size_t)(j0 + jl)*16 + c4];
            uint32_t* dst = &es[jl*SMS + c4*4];
            dst[0] = f2tf32(v.x); dst[1] = f2tf32(v.y);
            dst[2] = f2tf32(v.z); dst[3] = f2tf32(v.w);
            float4 kv = k2base[(size_t)(j0 + jl)*16 + c4];
            float* kd = &K2s[jl*SMS + c4*4];
            kd[0] = kv.x; kd[1] = kv.y; kd[2] = kv.z; kd[3] = kv.w;
        }
        __syncthreads();       // cnt reset + tiles visible
        if (t < 64) {
            unsigned a = adj[(size_t)bi * BN + j0 + t];
            adjf[t] = a ? 1 : 0;
            if (a) { int pos = atomicAdd(&cnt, 1); lst[pos] = t; }
        }
        __syncthreads();       // list/flags ready

        // ---- dense E2 path: warp handles 16 rows x all 8 heads ----
        float acc[8][4];
        #pragma unroll
        for (int nt = 0; nt < 8; ++nt)
            #pragma unroll
            for (int z = 0; z < 4; ++z) acc[nt][z] = 0.f;

        int rowA = (m_base + r)*SMS + cq;
        #pragma unroll 2
        for (int kc = 0; kc < 8; ++kc) {
            int k0 = kc * 8;
            uint32_t a0 = es[rowA + k0];
            uint32_t a1 = es[rowA + 8*SMS + k0];
            uint32_t a2 = es[rowA + k0 + 4];
            uint32_t a3 = es[rowA + 8*SMS + k0 + 4];
            int bb0 = (k0 + cq)*SMS + r;
            int bb1 = (k0 + cq + 4)*SMS + r;
            #pragma unroll
            for (int nt = 0; nt < 8; ++nt) {
                uint32_t b0 = A2s[bb0 + nt*8];
                uint32_t b1 = A2s[bb1 + nt*8];
                mma_tf32(acc[nt], a0, a1, a2, a3, b0, b1);
            }
        }

        // ---- epilogue: score[h,j] = sum_k Y[j,h*8+k]*K2[j,h*8+k] ----
        int jl0 = m_base + r, jl1 = jl0 + 8;
        #pragma unroll
        for (int h = 0; h < 8; ++h) {
            float2 ka = *(const float2*)&K2s[jl0*SMS + h*8 + 2*cq];
            float2 kb = *(const float2*)&K2s[jl1*SMS + h*8 + 2*cq];
            float s0 = acc[h][0]*ka.x + acc[h][1]*ka.y;
            float s1 = acc[h][2]*kb.x + acc[h][3]*kb.y;
            s0 += __shfl_xor_sync(0xffffffffu, s0, 1);
            s0 += __shfl_xor_sync(0xffffffffu, s0, 2);
            s1 += __shfl_xor_sync(0xffffffffu, s1, 1);
            s1 += __shfl_xor_sync(0xffffffffu, s1, 2);
            if (cq == 0) {
                size_t srow = ((size_t)(b*8 + h)*BN + i)*BN + j0;
                if (!adjf[jl0]) g_scores[srow + jl0] = s0;
                if (!adjf[jl1]) g_scores[srow + jl1] = s1;
            }
        }

        // ---- sparse E path: one adj column per warp ----
        int n = cnt;
        for (int q = w; q < n; q += 4) {
            int jl = lst[q];
            int j = j0 + jl;
            float y0 = 0.f, y1 = 0.f;
            #pragma unroll 8
            for (int d = 0; d < 64; ++d) {
                float ev = __uint_as_float(es[jl*SMS + d]);
                y0 += ev * WE[d*64 + lane];
                y1 += ev * WE[d*64 + 32 + lane];
            }
            y0 *= qs[lane];
            y1 *= qs[lane + 32];
            const float* kp = &g_K[((size_t)(b*BN + j))*64];
            float z0 = y0 * kp[lane];
            float z1 = y1 * kp[lane + 32];
            z0 += __shfl_xor_sync(0xffffffffu, z0, 1);
            z0 += __shfl_xor_sync(0xffffffffu, z0, 2);
            z0 += __shfl_xor_sync(0xffffffffu, z0, 4);
            z1 += __shfl_xor_sync(0xffffffffu, z1, 1);
            z1 += __shfl_xor_sync(0xffffffffu, z1, 2);
            z1 += __shfl_xor_sync(0xffffffffu, z1, 4);
            if ((lane & 7) == 0) {
                int h0 = lane >> 3;  // heads 0..3 (z0), 4..7 (z1)
                g_scores[((size_t)(b*8 + h0    )*BN + i)*BN + j] = z0;
                g_scores[((size_t)(b*8 + h0 + 4)*BN + i)*BN + j] = z1;
            }
        }
    }
}

// ---------------- K3: global max per (b,h) ----------------
__device__ __forceinline__ unsigned f2key(float f) {
    unsigned u = __float_as_uint(f);
    return (u & 0x80000000u) ? ~u : (u | 0x80000000u);
}
__device__ __forceinline__ float key2f(unsigned key) {
    unsigned u = (key & 0x80000000u) ? (key ^ 0x80000000u) : ~key;
    return __uint_as_float(u);
}
__global__ void __launch_bounds__(256) k3_max() {
    int bh = blockIdx.x >> 4, ch = blockIdx.x & 15;
    const float4* base = (const float4*)(g_scores + (size_t)bh*BN*BN + (size_t)ch*16384);
    float m = -INFINITY;
    for (int idx = threadIdx.x; idx < 4096; idx += 256) {
        float4 v = base[idx];
        m = fmaxf(m, fmaxf(fmaxf(v.x, v.y), fmaxf(v.z, v.w)));
    }
    #pragma unroll
    for (int off = 16; off; off >>= 1) m = fmaxf(m, __shfl_xor_sync(0xffffffffu, m, off));
    __shared__ float red[8];
    if ((threadIdx.x & 31) == 0) red[threadIdx.x >> 5] = m;
    __syncthreads();
    if (threadIdx.x < 8) {
        float mm = red[threadIdx.x];
        mm = fmaxf(mm, __shfl_xor_sync(0x000000ffu, mm, 4));
        mm = fmaxf(mm, __shfl_xor_sync(0x000000ffu, mm, 2));
        mm = fmaxf(mm, __shfl_xor_sync(0x000000ffu, mm, 1));
        if (threadIdx.x == 0) atomicMax(&g_maxbits[bh], f2key(mm));
    }
}

// ---------------- K4: exp/mask/k_RW + rowsum + att@V ----------------
__global__ void __launch_bounds__(256) k4_att(
    const float* __restrict__ kRW, const float* __restrict__ mask)
{
    extern __shared__ float Vs[];  // [64][513] : Vs[c*513 + j]
    int b  = blockIdx.y;
    int i0 = blockIdx.x * 8;
    int t = threadIdx.x, lane = t & 31, h = t >> 5;

    for (int idx = t; idx < BN*64; idx += 256) {
        int j = idx >> 6, c = idx & 63;
        Vs[c*513 + j] = g_V[((size_t)(b*BN + j))*64 + c];
    }
    __syncthreads();

    float mx = key2f(g_maxbits[b*8 + h]);

    for (int ii = 0; ii < 8; ++ii) {
        int i = i0 + ii;
        float mi = mask[b*BN + i];
        const float* sp = g_scores + ((size_t)(b*8 + h)*BN + i)*BN;
        const float* wp = kRW + ((size_t)(b*BN + i))*BN;
        float pden = 0.f;
        float pav[8];
        #pragma unroll
        for (int k = 0; k < 8; ++k) pav[k] = 0.f;

        for (int jt = 0; jt < 16; ++jt) {
            int j = jt*32 + lane;
            float pw = expf(sp[j] - mx) * wp[j] * mask[b*BN + j] * mi;
            pden += pw;
            #pragma unroll
            for (int k = 0; k < 8; ++k) pav[k] += pw * Vs[(h*8 + k)*513 + j];
        }
        #pragma unroll
        for (int off = 16; off; off >>= 1) {
            pden += __shfl_down_sync(0xffffffffu, pden, off);
            #pragma unroll
            for (int k = 0; k < 8; ++k) pav[k] += __shfl_down_sync(0xffffffffu, pav[k], off);
        }
        if (lane == 0) {
            float inv = 1.f / fmaxf(pden, 1e-6f);
            float4* op = (float4*)&g_hatt[((size_t)(b*BN + i))*64 + h*8];
            op[0] = make_float4(pav[0]*inv, pav[1]*inv, pav[2]*inv, pav[3]*inv);
            op[1] = make_float4(pav[4]*inv, pav[5]*inv, pav[6]*inv, pav[7]*inv);
        }
    }
}

// ---------------- K5: O-proj + residual + LN2 + FFN + residual ----------------
__global__ void __launch_bounds__(64) k5_out(
    const float* __restrict__ hin, const float* __restrict__ OW,
    const float* __restrict__ Ob, const float* __restrict__ g2,
    const float* __restrict__ b2, const float* __restrict__ Wf1,
    const float* __restrict__ bf1, const float* __restrict__ Wf2,
    const float* __restrict__ bf2, float* __restrict__ out)
{
    int row = blockIdx.x;
    int t = threadIdx.x;
    __shared__ float has[64], ys[64], hid[128];
    __shared__ float red[4];

    has[t] = g_hatt[row*64 + t];
    __syncthreads();

    float a = hin[row*64 + t] + Ob[t];
    #pragma unroll 8
    for (int d = 0; d < 64; ++d) a += has[d] * OW[d*64 + t];

    float s = a, sq = a*a;
    #pragma unroll
    for (int off = 16; off; off >>= 1) {
        s  += __shfl_down_sync(0xffffffffu, s,  off);
        sq += __shfl_down_sync(0xffffffffu, sq, off);
    }
    int wid = t >> 5, lane = t & 31;
    if (lane == 0) { red[wid*2] = s; red[wid*2+1] = sq; }
    __syncthreads();
    float S  = red[0] + red[2];
    float SQ = red[1] + red[3];
    float mean = S * (1.f/64.f);
    float var  = SQ * (1.f/64.f) - mean*mean;
    float rinv = 1.f / sqrtf(var + 1e-5f);
    ys[t] = (a - mean) * rinv * g2[t] + b2[t];
    __syncthreads();

    float h0 = bf1[t], h1 = bf1[t + 64];
    #pragma unroll 8
    for (int d = 0; d < 64; ++d) {
        float x = ys[d];
        h0 += x * Wf1[d*128 + t];
        h1 += x * Wf1[d*128 + t + 64];
    }
    hid[t]      = fmaxf(h0, 0.f);
    hid[t + 64] = fmaxf(h1, 0.f);
    __syncthreads();

    float o = a + bf2[t];
    #pragma unroll 8
    for (int c = 0; c < 128; ++c) o += hid[c] * Wf2[c*64 + t];
    out[row*64 + t] = o;
}

// ---------------- launch ----------------
extern "C" void kernel_launch(void* const* d_in, const int* in_sizes, int n_in,
                              void* d_out, int out_size)
{
    const float* h    = (const float*)d_in[0];
    const float* p    = (const float*)d_in[1];
    const float* e    = (const float*)d_in[2];
    const float* kRW  = (const float*)d_in[3];
    const float* mask = (const float*)d_in[4];
    const unsigned* adj = (const unsigned*)d_in[5];
    const float* WQ   = (const float*)d_in[6];
    const float* WK   = (const float*)d_in[7];
    const float* WV   = (const float*)d_in[8];
    const float* WQ2  = (const float*)d_in[9];
    const float* WK2  = (const float*)d_in[10];
    const float* WE   = (const float*)d_in[11];
    const float* WE2  = (const float*)d_in[12];
    const float* OW   = (const float*)d_in[13];
    const float* Ob   = (const float*)d_in[14];
    const float* g1   = (const float*)d_in[15];
    const float* b1   = (const float*)d_in[16];
    const float* g2   = (const float*)d_in[17];
    const float* b2   = (const float*)d_in[18];
    const float* Wf1  = (const float*)d_in[19];
    const float* bf1  = (const float*)d_in[20];
    const float* Wf2  = (const float*)d_in[21];
    const float* bf2  = (const float*)d_in[22];
    float* out = (float*)d_out;

    static int attr_done = 0;
    const int k2_smem = 3 * 64 * SMS * 4;  // 55296 bytes
    cudaFuncSetAttribute(k2_scores, cudaFuncAttributeMaxDynamicSharedMemorySize, k2_smem);
    cudaFuncSetAttribute(k4_att, cudaFuncAttributeMaxDynamicSharedMemorySize, 64*513*4);
    (void)attr_done;

    k0_init<<<1, 32>>>();
    k1_proj<<<NROWS, 64>>>(h, p, g1, b1, WQ, WK, WV, WQ2, WK2);
    k2_scores<<<NROWS, 128, k2_smem>>>(e, adj, WE, WE2);
    k3_max<<<BH*16, 256>>>();
    k4_att<<<dim3(64, BB), 256, 64*513*4>>>(kRW, mask);
    k5_out<<<NROWS, 64>>>(h, OW, Ob, g2, b2, Wf1, bf1, Wf2, bf2, out);
}

// round 3
// speedup vs baseline: 1.3800x; 1.0029x over previous
#include <cuda_runtime.h>
#include <math.h>
#include <stdint.h>

// Problem constants
#define BB 4
#define BN 512
#define DD 64
#define HH 8
#define BH (BB*HH)        // 32
#define NROWS (BB*BN)     // 2048

// ---------------- scratch (static device globals; no allocs) ----------------
__device__ float g_Q [NROWS*DD];
__device__ float g_K [NROWS*DD];   // pre-scaled by DH^-0.5
__device__ float g_V [NROWS*DD];
__device__ float g_Q2[NROWS*DD];
__device__ float g_K2[NROWS*DD];   // pre-scaled
__device__ float g_scores[(size_t)BH*BN*BN];  // 33.5 MB
__device__ unsigned g_maxbits[BH];
__device__ float g_hatt[NROWS*DD];

// ---------------- helpers ----------------
__device__ __forceinline__ uint32_t f2tf32(float f) {
    uint32_t r;
    asm("cvt.rna.tf32.f32 %0, %1;" : "=r"(r) : "f"(f));
    return r;
}
__device__ __forceinline__ void mma_tf32(float c[4],
    uint32_t a0, uint32_t a1, uint32_t a2, uint32_t a3,
    uint32_t b0, uint32_t b1)
{
    asm volatile(
        "mma.sync.aligned.m16n8k8.row.col.f32.tf32.tf32.f32 "
        "{%0,%1,%2,%3}, {%4,%5,%6,%7}, {%8,%9}, {%0,%1,%2,%3};"
        : "+f"(c[0]), "+f"(c[1]), "+f"(c[2]), "+f"(c[3])
        : "r"(a0), "r"(a1), "r"(a2), "r"(a3), "r"(b0), "r"(b1));
}

// ---------------- K0: init max accumulators ----------------
__global__ void k0_init() {
    if (threadIdx.x < BH) g_maxbits[threadIdx.x] = 0u;  // key-space -inf
}

// ---------------- K1: x = LN(h+p); Q,K,V,Q2,K2 projections ----------------
__global__ void __launch_bounds__(64) k1_proj(
    const float* __restrict__ h, const float* __restrict__ p,
    const float* __restrict__ g1, const float* __restrict__ b1,
    const float* __restrict__ WQ, const float* __restrict__ WK,
    const float* __restrict__ WV, const float* __restrict__ WQ2,
    const float* __restrict__ WK2)
{
    int row = blockIdx.x;
    int t = threadIdx.x;
    __shared__ float xs[64];
    __shared__ float red[4];

    float v = h[row*64 + t] + p[row*64 + t];
    float s = v, sq = v*v;
    #pragma unroll
    for (int off = 16; off; off >>= 1) {
        s  += __shfl_down_sync(0xffffffffu, s,  off);
        sq += __shfl_down_sync(0xffffffffu, sq, off);
    }
    int wid = t >> 5, lane = t & 31;
    if (lane == 0) { red[wid*2] = s; red[wid*2+1] = sq; }
    __syncthreads();
    float S  = red[0] + red[2];
    float SQ = red[1] + red[3];
    float mean = S * (1.f/64.f);
    float var  = SQ * (1.f/64.f) - mean*mean;
    float rinv = 1.f / sqrtf(var + 1e-5f);
    xs[t] = (v - mean) * rinv * g1[t] + b1[t];
    __syncthreads();

    float q = 0.f, k = 0.f, vv = 0.f, q2 = 0.f, k2 = 0.f;
    #pragma unroll 8
    for (int d = 0; d < 64; ++d) {
        float x = xs[d];
        q  += x * WQ [d*64 + t];
        k  += x * WK [d*64 + t];
        vv += x * WV [d*64 + t];
        q2 += x * WQ2[d*64 + t];
        k2 += x * WK2[d*64 + t];
    }
    const float sc = 0.35355339059327373f;  // 8^-0.5
    g_Q [row*64 + t] = q;
    g_K [row*64 + t] = k * sc;
    g_V [row*64 + t] = vv;
    g_Q2[row*64 + t] = q2;
    g_K2[row*64 + t] = k2 * sc;
}

// ---------------- K2: tensor-core fused scores ----------------
// Block = one (b,i), 128 threads = 4 warps.
// Dense: Y = e_tile[64x64] @ A2_i[64x64] via tf32 mma, then per-row 8-dot with K2.
// Sparse (adj set): cooperative Q*K*E matvec, one column per warp.
#define SMS 72   // padded smem row stride (bank-conflict-free)
__global__ void __launch_bounds__(128) k2_scores(
    const float* __restrict__ e, const unsigned* __restrict__ adj,
    const float* __restrict__ WE, const float* __restrict__ WE2)
{
    extern __shared__ uint32_t dyn[];
    uint32_t* es  = dyn;                 // [64][SMS] tf32 bits, row=j, col=d
    uint32_t* A2s = dyn + 64*SMS;        // [64][SMS] tf32 bits, row=d, col=hk
    float*    K2s = (float*)(dyn + 2*64*SMS);  // [64][SMS] fp32, row=j, col=hk

    __shared__ float qs[64], q2s[64];
    __shared__ int lst[64];
    __shared__ int cnt;
    __shared__ unsigned char adjf[64];

    int bi = blockIdx.x;
    int b = bi >> 9, i = bi & 511;
    int t = threadIdx.x;
    int w = t >> 5, lane = t & 31;
    int r = lane >> 2, cq = lane & 3;
    int m_base = w * 16;

    if (t < 64) qs[t] = g_Q[bi*64 + t];
    else        q2s[t-64] = g_Q2[bi*64 + (t-64)];
    __syncthreads();
    for (int idx = t; idx < 4096; idx += 128) {
        int d = idx >> 6, hk = idx & 63;
        A2s[d*SMS + hk] = f2tf32(WE2[idx] * q2s[hk]);
    }

    const float4* ebase  = (const float4*)(e + (size_t)bi * BN * 64);
    const float4* k2base = (const float4*)(g_K2 + (size_t)b * BN * 64);

    for (int jt = 0; jt < 8; ++jt) {
        int j0 = jt * 64;
        __syncthreads();       // prior tile fully consumed (also covers A2s build)
        if (t == 0) cnt = 0;
        // stage e tile (cvt to tf32) and K2 tile
        for (int idx = t; idx < 1024; idx += 128) {
            int jl = idx >> 4, c4 = idx & 15;
            float4 v = ebase[(size_t)(j0 + jl)*16 + c4];
            uint32_t* dst = &es[jl*SMS + c4*4];
            dst[0] = f2tf32(v.x); dst[1] = f2tf32(v.y);
            dst[2] = f2tf32(v.z); dst[3] = f2tf32(v.w);
            float4 kv = k2base[(size_t)(j0 + jl)*16 + c4];
            float* kd = &K2s[jl*SMS + c4*4];
            kd[0] = kv.x; kd[1] = kv.y; kd[2] = kv.z; kd[3] = kv.w;
        }
        __syncthreads();       // cnt reset + tiles visible
        if (t < 64) {
            unsigned a = adj[(size_t)bi * BN + j0 + t];
            adjf[t] = a ? 1 : 0;
            if (a) { int pos = atomicAdd(&cnt, 1); lst[pos] = t; }
        }
        __syncthreads();       // list/flags ready

        // ---- dense E2 path: warp handles 16 rows x all 8 heads ----
        float acc[8][4];
        #pragma unroll
        for (int nt = 0; nt < 8; ++nt)
            #pragma unroll
            for (int z = 0; z < 4; ++z) acc[nt][z] = 0.f;

        int rowA = (m_base + r)*SMS + cq;
        #pragma unroll 2
        for (int kc = 0; kc < 8; ++kc) {
            int k0 = kc * 8;
            uint32_t a0 = es[rowA + k0];
            uint32_t a1 = es[rowA + 8*SMS + k0];
            uint32_t a2 = es[rowA + k0 + 4];
            uint32_t a3 = es[rowA + 8*SMS + k0 + 4];
            int bb0 = (k0 + cq)*SMS + r;
            int bb1 = (k0 + cq + 4)*SMS + r;
            #pragma unroll
            for (int nt = 0; nt < 8; ++nt) {
                uint32_t b0 = A2s[bb0 + nt*8];
                uint32_t b1 = A2s[bb1 + nt*8];
                mma_tf32(acc[nt], a0, a1, a2, a3, b0, b1);
            }
        }

        // ---- epilogue: score[h,j] = sum_k Y[j,h*8+k]*K2[j,h*8+k] ----
        int jl0 = m_base + r, jl1 = jl0 + 8;
        #pragma unroll
        for (int h = 0; h < 8; ++h) {
            float2 ka = *(const float2*)&K2s[jl0*SMS + h*8 + 2*cq];
            float2 kb = *(const float2*)&K2s[jl1*SMS + h*8 + 2*cq];
            float s0 = acc[h][0]*ka.x + acc[h][1]*ka.y;
            float s1 = acc[h][2]*kb.x + acc[h][3]*kb.y;
            s0 += __shfl_xor_sync(0xffffffffu, s0, 1);
            s0 += __shfl_xor_sync(0xffffffffu, s0, 2);
            s1 += __shfl_xor_sync(0xffffffffu, s1, 1);
            s1 += __shfl_xor_sync(0xffffffffu, s1, 2);
            if (cq == 0) {
                size_t srow = ((size_t)(b*8 + h)*BN + i)*BN + j0;
                if (!adjf[jl0]) g_scores[srow + jl0] = s0;
                if (!adjf[jl1]) g_scores[srow + jl1] = s1;
            }
        }

        // ---- sparse E path: one adj column per warp ----
        int n = cnt;
        for (int q = w; q < n; q += 4) {
            int jl = lst[q];
            int j = j0 + jl;
            float y0 = 0.f, y1 = 0.f;
            #pragma unroll 8
            for (int d = 0; d < 64; ++d) {
                float ev = __uint_as_float(es[jl*SMS + d]);
                y0 += ev * WE[d*64 + lane];
                y1 += ev * WE[d*64 + 32 + lane];
            }
            y0 *= qs[lane];
            y1 *= qs[lane + 32];
            const float* kp = &g_K[((size_t)(b*BN + j))*64];
            float z0 = y0 * kp[lane];
            float z1 = y1 * kp[lane + 32];
            z0 += __shfl_xor_sync(0xffffffffu, z0, 1);
            z0 += __shfl_xor_sync(0xffffffffu, z0, 2);
            z0 += __shfl_xor_sync(0xffffffffu, z0, 4);
            z1 += __shfl_xor_sync(0xffffffffu, z1, 1);
            z1 += __shfl_xor_sync(0xffffffffu, z1, 2);
            z1 += __shfl_xor_sync(0xffffffffu, z1, 4);
            if ((lane & 7) == 0) {
                int h0 = lane >> 3;  // heads 0..3 (z0), 4..7 (z1)
                g_scores[((size_t)(b*8 + h0    )*BN + i)*BN + j] = z0;
                g_scores[((size_t)(b*8 + h0 + 4)*BN + i)*BN + j] = z1;
            }
        }
    }
}

// ---------------- K3: global max per (b,h) ----------------
__device__ __forceinline__ unsigned f2key(float f) {
    unsigned u = __float_as_uint(f);
    return (u & 0x80000000u) ? ~u : (u | 0x80000000u);
}
__device__ __forceinline__ float key2f(unsigned key) {
    unsigned u = (key & 0x80000000u) ? (key ^ 0x80000000u) : ~key;
    return __uint_as_float(u);
}
__global__ void __launch_bounds__(256) k3_max() {
    int bh = blockIdx.x >> 4, ch = blockIdx.x & 15;
    const float4* base = (const float4*)(g_scores + (size_t)bh*BN*BN + (size_t)ch*16384);
    float m = -INFINITY;
    for (int idx = threadIdx.x; idx < 4096; idx += 256) {
        float4 v = base[idx];
        m = fmaxf(m, fmaxf(fmaxf(v.x, v.y), fmaxf(v.z, v.w)));
    }
    #pragma unroll
    for (int off = 16; off; off >>= 1) m = fmaxf(m, __shfl_xor_sync(0xffffffffu, m, off));
    __shared__ float red[8];
    if ((threadIdx.x & 31) == 0) red[threadIdx.x >> 5] = m;
    __syncthreads();
    if (threadIdx.x < 8) {
        float mm = red[threadIdx.x];
        mm = fmaxf(mm, __shfl_xor_sync(0x000000ffu, mm, 4));
        mm = fmaxf(mm, __shfl_xor_sync(0x000000ffu, mm, 2));
        mm = fmaxf(mm, __shfl_xor_sync(0x000000ffu, mm, 1));
        if (threadIdx.x == 0) atomicMax(&g_maxbits[bh], f2key(mm));
    }
}

// ---------------- K4: exp/mask/k_RW + rowsum + att@V ----------------
__global__ void __launch_bounds__(256) k4_att(
    const float* __restrict__ kRW, const float* __restrict__ mask)
{
    extern __shared__ float Vs[];  // [64][513] : Vs[c*513 + j]
    int b  = blockIdx.y;
    int i0 = blockIdx.x * 8;
    int t = threadIdx.x, lane = t & 31, h = t >> 5;

    for (int idx = t; idx < BN*64; idx += 256) {
        int j = idx >> 6, c = idx & 63;
        Vs[c*513 + j] = g_V[((size_t)(b*BN + j))*64 + c];
    }
    __syncthreads();

    float mx = key2f(g_maxbits[b*8 + h]);

    for (int ii = 0; ii < 8; ++ii) {
        int i = i0 + ii;
        float mi = mask[b*BN + i];
        const float* sp = g_scores + ((size_t)(b*8 + h)*BN + i)*BN;
        const float* wp = kRW + ((size_t)(b*BN + i))*BN;
        float pden = 0.f;
        float pav[8];
        #pragma unroll
        for (int k = 0; k < 8; ++k) pav[k] = 0.f;

        for (int jt = 0; jt < 16; ++jt) {
            int j = jt*32 + lane;
            float pw = expf(sp[j] - mx) * wp[j] * mask[b*BN + j] * mi;
            pden += pw;
            #pragma unroll
            for (int k = 0; k < 8; ++k) pav[k] += pw * Vs[(h*8 + k)*513 + j];
        }
        #pragma unroll
        for (int off = 16; off; off >>= 1) {
            pden += __shfl_down_sync(0xffffffffu, pden, off);
            #pragma unroll
            for (int k = 0; k < 8; ++k) pav[k] += __shfl_down_sync(0xffffffffu, pav[k], off);
        }
        if (lane == 0) {
            float inv = 1.f / fmaxf(pden, 1e-6f);
            float4* op = (float4*)&g_hatt[((size_t)(b*BN + i))*64 + h*8];
            op[0] = make_float4(pav[0]*inv, pav[1]*inv, pav[2]*inv, pav[3]*inv);
            op[1] = make_float4(pav[4]*inv, pav[5]*inv, pav[6]*inv, pav[7]*inv);
        }
    }
}

// ---------------- K5: O-proj + residual + LN2 + FFN + residual ----------------
__global__ void __launch_bounds__(64) k5_out(
    const float* __restrict__ hin, const float* __restrict__ OW,
    const float* __restrict__ Ob, const float* __restrict__ g2,
    const float* __restrict__ b2, const float* __restrict__ Wf1,
    const float* __restrict__ bf1, const float* __restrict__ Wf2,
    const float* __restrict__ bf2, float* __restrict__ out)
{
    int row = blockIdx.x;
    int t = threadIdx.x;
    __shared__ float has[64], ys[64], hid[128];
    __shared__ float red[4];

    has[t] = g_hatt[row*64 + t];
    __syncthreads();

    float a = hin[row*64 + t] + Ob[t];
    #pragma unroll 8
    for (int d = 0; d < 64; ++d) a += has[d] * OW[d*64 + t];

    float s = a, sq = a*a;
    #pragma unroll
    for (int off = 16; off; off >>= 1) {
        s  += __shfl_down_sync(0xffffffffu, s,  off);
        sq += __shfl_down_sync(0xffffffffu, sq, off);
    }
    int wid = t >> 5, lane = t & 31;
    if (lane == 0) { red[wid*2] = s; red[wid*2+1] = sq; }
    __syncthreads();
    float S  = red[0] + red[2];
    float SQ = red[1] + red[3];
    float mean = S * (1.f/64.f);
    float var  = SQ * (1.f/64.f) - mean*mean;
    float rinv = 1.f / sqrtf(var + 1e-5f);
    ys[t] = (a - mean) * rinv * g2[t] + b2[t];
    __syncthreads();

    float h0 = bf1[t], h1 = bf1[t + 64];
    #pragma unroll 8
    for (int d = 0; d < 64; ++d) {
        float x = ys[d];
        h0 += x * Wf1[d*128 + t];
        h1 += x * Wf1[d*128 + t + 64];
    }
    hid[t]      = fmaxf(h0, 0.f);
    hid[t + 64] = fmaxf(h1, 0.f);
    __syncthreads();

    float o = a + bf2[t];
    #pragma unroll 8
    for (int c = 0; c < 128; ++c) o += hid[c] * Wf2[c*64 + t];
    out[row*64 + t] = o;
}

// ---------------- launch ----------------
extern "C" void kernel_launch(void* const* d_in, const int* in_sizes, int n_in,
                              void* d_out, int out_size)
{
    const float* h    = (const float*)d_in[0];
    const float* p    = (const float*)d_in[1];
    const float* e    = (const float*)d_in[2];
    const float* kRW  = (const float*)d_in[3];
    const float* mask = (const float*)d_in[4];
    const unsigned* adj = (const unsigned*)d_in[5];
    const float* WQ   = (const float*)d_in[6];
    const float* WK   = (const float*)d_in[7];
    const float* WV   = (const float*)d_in[8];
    const float* WQ2  = (const float*)d_in[9];
    const float* WK2  = (const float*)d_in[10];
    const float* WE   = (const float*)d_in[11];
    const float* WE2  = (const float*)d_in[12];
    const float* OW   = (const float*)d_in[13];
    const float* Ob   = (const float*)d_in[14];
    const float* g1   = (const float*)d_in[15];
    const float* b1   = (const float*)d_in[16];
    const float* g2   = (const float*)d_in[17];
    const float* b2   = (const float*)d_in[18];
    const float* Wf1  = (const float*)d_in[19];
    const float* bf1  = (const float*)d_in[20];
    const float* Wf2  = (const float*)d_in[21];
    const float* bf2  = (const float*)d_in[22];
    float* out = (float*)d_out;

    static int attr_done = 0;
    const int k2_smem = 3 * 64 * SMS * 4;  // 55296 bytes
    cudaFuncSetAttribute(k2_scores, cudaFuncAttributeMaxDynamicSharedMemorySize, k2_smem);
    cudaFuncSetAttribute(k4_att, cudaFuncAttributeMaxDynamicSharedMemorySize, 64*513*4);
    (void)attr_done;

    k0_init<<<1, 32>>>();
    k1_proj<<<NROWS, 64>>>(h, p, g1, b1, WQ, WK, WV, WQ2, WK2);
    k2_scores<<<NROWS, 128, k2_smem>>>(e, adj, WE, WE2);
    k3_max<<<BH*16, 256>>>();
    k4_att<<<dim3(64, BB), 256, 64*513*4>>>(kRW, mask);
    k5_out<<<NROWS, 64>>>(h, OW, Ob, g2, b2, Wf1, bf1, Wf2, bf2, out);
}

// round 5
// speedup vs baseline: 1.5900x; 1.1522x over previous
#include <cuda_runtime.h>
#include <cuda_bf16.h>
#include <math.h>
#include <stdint.h>

// Problem constants
#define BB 4
#define BN 512
#define BH 32
#define NROWS 2048

// ---------------- scratch (static device globals; no allocs) ----------------
__device__ float g_Q [NROWS*64];
__device__ float g_K [NROWS*64];   // pre-scaled by DH^-0.5
__device__ float g_V [NROWS*64];
__device__ float g_Q2[NROWS*64];
__device__ float g_K2[NROWS*64];   // pre-scaled
__device__ float g_WE2T[64*64];    // W_E2^T : [hk][d]
__device__ float g_scores[(size_t)BH*BN*BN];  // 33.5 MB
__device__ unsigned g_maxbits[BH];
__device__ float g_hatt[NROWS*64];

// ---------------- helpers ----------------
__device__ __forceinline__ void mma_bf16(float c[4],
    uint32_t a0, uint32_t a1, uint32_t a2, uint32_t a3,
    uint32_t b0, uint32_t b1)
{
    asm volatile(
        "mma.sync.aligned.m16n8k16.row.col.f32.bf16.bf16.f32 "
        "{%0,%1,%2,%3}, {%4,%5,%6,%7}, {%8,%9}, {%0,%1,%2,%3};"
        : "+f"(c[0]), "+f"(c[1]), "+f"(c[2]), "+f"(c[3])
        : "r"(a0), "r"(a1), "r"(a2), "r"(a3), "r"(b0), "r"(b1));
}
__device__ __forceinline__ unsigned f2key(float f) {
    unsigned u = __float_as_uint(f);
    return (u & 0x80000000u) ? ~u : (u | 0x80000000u);
}
__device__ __forceinline__ float key2f(unsigned key) {
    unsigned u = (key & 0x80000000u) ? (key ^ 0x80000000u) : ~key;
    return __uint_as_float(u);
}

// ---------------- K0: init max accumulators + transpose W_E2 ----------------
__global__ void __launch_bounds__(256) k0_init(const float* __restrict__ WE2) {
    int t = threadIdx.x;
    if (t < BH) g_maxbits[t] = 0u;  // key-space -inf
    for (int i = t; i < 4096; i += 256) {
        int d = i >> 6, c = i & 63;
        g_WE2T[c*64 + d] = WE2[i];
    }
}

// ---------------- K1: x = LN(h+p); Q,K,V,Q2,K2 projections ----------------
__global__ void __launch_bounds__(64) k1_proj(
    const float* __restrict__ h, const float* __restrict__ p,
    const float* __restrict__ g1, const float* __restrict__ b1,
    const float* __restrict__ WQ, const float* __restrict__ WK,
    const float* __restrict__ WV, const float* __restrict__ WQ2,
    const float* __restrict__ WK2)
{
    int row = blockIdx.x;
    int t = threadIdx.x;
    __shared__ float xs[64];
    __shared__ float red[4];

    float v = h[row*64 + t] + p[row*64 + t];
    float s = v, sq = v*v;
    #pragma unroll
    for (int off = 16; off; off >>= 1) {
        s  += __shfl_down_sync(0xffffffffu, s,  off);
        sq += __shfl_down_sync(0xffffffffu, sq, off);
    }
    int wid = t >> 5, lane = t & 31;
    if (lane == 0) { red[wid*2] = s; red[wid*2+1] = sq; }
    __syncthreads();
    float S  = red[0] + red[2];
    float SQ = red[1] + red[3];
    float mean = S * (1.f/64.f);
    float var  = SQ * (1.f/64.f) - mean*mean;
    float rinv = rsqrtf(var + 1e-5f);
    xs[t] = (v - mean) * rinv * g1[t] + b1[t];
    __syncthreads();

    float q = 0.f, k = 0.f, vv = 0.f, q2 = 0.f, k2 = 0.f;
    #pragma unroll 8
    for (int d = 0; d < 64; ++d) {
        float x = xs[d];
        q  += x * WQ [d*64 + t];
        k  += x * WK [d*64 + t];
        vv += x * WV [d*64 + t];
        q2 += x * WQ2[d*64 + t];
        k2 += x * WK2[d*64 + t];
    }
    const float sc = 0.35355339059327373f;  // 8^-0.5
    g_Q [row*64 + t] = q;
    g_K [row*64 + t] = k * sc;
    g_V [row*64 + t] = vv;
    g_Q2[row*64 + t] = q2;
    g_K2[row*64 + t] = k2 * sc;
}

// ---------------- K2: bf16 m16n8k16 tensor-core fused scores ----------------
// Block = one (b,i), 128 threads = 4 warps.
// Dense: Y = e_tile[64x64] @ A2_i^T via bf16 mma (A2_i[hk][d] = W_E2^T * Q2),
//        then per-row 8-dot with K2.
// Sparse (adj set): cooperative Q*K*E matvec, one column per warp.
#define SMSB 72   // bf16 row stride for es/A2s (conflict-free)
#define SMSF 68   // fp32 row stride for K2s
__global__ void __launch_bounds__(128) k2_scores(
    const float* __restrict__ e, const unsigned* __restrict__ adj,
    const float* __restrict__ WE)
{
    extern __shared__ char dyn[];
    __nv_bfloat16* es  = (__nv_bfloat16*)dyn;                    // [64][SMSB] row=j, col=d
    __nv_bfloat16* A2s = (__nv_bfloat16*)(dyn + 64*SMSB*2);      // [64][SMSB] row=hk, col=d
    float*         K2s = (float*)        (dyn + 2*64*SMSB*2);    // [64][SMSF] row=j, col=hk

    __shared__ float qs[64], q2s[64];
    __shared__ int lst[64];
    __shared__ int cnt;
    __shared__ unsigned char adjf[64];

    int bi = blockIdx.x;
    int b = bi >> 9, i = bi & 511;
    int t = threadIdx.x;
    int w = t >> 5, lane = t & 31;
    int r = lane >> 2, cq = lane & 3;
    int m_base = w * 16;

    if (t < 64) qs[t] = g_Q[bi*64 + t];
    else        q2s[t-64] = g_Q2[bi*64 + (t-64)];
    __syncthreads();
    // A2s[hk][d] = W_E2^T[hk][d] * q2[hk], bf16
    #pragma unroll
    for (int it = 0; it < 16; ++it) {
        int idx = t + it*128;              // pair index, 2048 total
        int hk = idx >> 5, dp = idx & 31;
        float2 wv = *(const float2*)&g_WE2T[hk*64 + dp*2];
        float qv = q2s[hk];
        __nv_bfloat162 bv = __floats2bfloat162_rn(wv.x*qv, wv.y*qv);
        *(uint32_t*)&A2s[hk*SMSB + dp*2] = *(uint32_t*)&bv;
    }

    const float4* ebase  = (const float4*)(e + (size_t)bi * BN * 64);
    const float4* k2base = (const float4*)(g_K2 + (size_t)b * BN * 64);

    for (int jt = 0; jt < 8; ++jt) {
        int j0 = jt * 64;
        __syncthreads();       // prior tile fully consumed (also covers A2s build)
        if (t == 0) cnt = 0;
        // stage e tile (fp32 -> bf16) and K2 tile (fp32)
        #pragma unroll
        for (int it = 0; it < 8; ++it) {
            int idx = t + it*128;          // float4 index, 1024 total
            int jl = idx >> 4, c4 = idx & 15;
            float4 v = ebase[(size_t)(j0 + jl)*16 + c4];
            __nv_bfloat162 lo = __floats2bfloat162_rn(v.x, v.y);
            __nv_bfloat162 hi = __floats2bfloat162_rn(v.z, v.w);
            uint2 pk = { *(uint32_t*)&lo, *(uint32_t*)&hi };
            *(uint2*)&es[jl*SMSB + c4*4] = pk;
            float4 kv = k2base[(size_t)(j0 + jl)*16 + c4];
            *(float4*)&K2s[jl*SMSF + c4*4] = kv;
        }
        __syncthreads();       // cnt reset + tiles visible
        if (t < 64) {
            unsigned a = adj[(size_t)bi * BN + j0 + t];
            adjf[t] = a ? 1 : 0;
            if (a) { int pos = atomicAdd(&cnt, 1); lst[pos] = t; }
        }
        __syncthreads();       // list/flags ready

        // ---- dense E2 path: warp computes 16 rows x 64 hk, K=64 ----
        float acc[8][4];
        #pragma unroll
        for (int nt = 0; nt < 8; ++nt)
            #pragma unroll
            for (int z = 0; z < 4; ++z) acc[nt][z] = 0.f;

        int a_row0 = (m_base + r)*SMSB;
        int a_row1 = a_row0 + 8*SMSB;
        #pragma unroll
        for (int kc = 0; kc < 4; ++kc) {
            int k0 = kc*16 + cq*2;
            uint32_t a0 = *(const uint32_t*)&es[a_row0 + k0];
            uint32_t a1 = *(const uint32_t*)&es[a_row1 + k0];
            uint32_t a2 = *(const uint32_t*)&es[a_row0 + k0 + 8];
            uint32_t a3 = *(const uint32_t*)&es[a_row1 + k0 + 8];
            #pragma unroll
            for (int nt = 0; nt < 8; ++nt) {
                int n = nt*8 + r;
                uint32_t b0 = *(const uint32_t*)&A2s[n*SMSB + k0];
                uint32_t b1 = *(const uint32_t*)&A2s[n*SMSB + k0 + 8];
                mma_bf16(acc[nt], a0, a1, a2, a3, b0, b1);
            }
        }

        // ---- epilogue: score[h,j] = sum_k Y[j,h*8+k]*K2[j,h*8+k] ----
        int jl0 = m_base + r, jl1 = jl0 + 8;
        #pragma unroll
        for (int h = 0; h < 8; ++h) {
            float2 ka = *(const float2*)&K2s[jl0*SMSF + h*8 + 2*cq];
            float2 kb = *(const float2*)&K2s[jl1*SMSF + h*8 + 2*cq];
            float s0 = acc[h][0]*ka.x + acc[h][1]*ka.y;
            float s1 = acc[h][2]*kb.x + acc[h][3]*kb.y;
            s0 += __shfl_xor_sync(0xffffffffu, s0, 1);
            s0 += __shfl_xor_sync(0xffffffffu, s0, 2);
            s1 += __shfl_xor_sync(0xffffffffu, s1, 1);
            s1 += __shfl_xor_sync(0xffffffffu, s1, 2);
            if (cq == 0) {
                size_t srow = ((size_t)(b*8 + h)*BN + i)*BN + j0;
                if (!adjf[jl0]) g_scores[srow + jl0] = s0;
                if (!adjf[jl1]) g_scores[srow + jl1] = s1;
            }
        }

        // ---- sparse E path: one adj column per warp ----
        int n = cnt;
        for (int q = w; q < n; q += 4) {
            int jl = lst[q];
            int j = j0 + jl;
            float y0 = 0.f, y1 = 0.f;
            #pragma unroll 8
            for (int d = 0; d < 64; ++d) {
                float ev = __bfloat162float(es[jl*SMSB + d]);
                y0 += ev * WE[d*64 + lane];
                y1 += ev * WE[d*64 + 32 + lane];
            }
            y0 *= qs[lane];
            y1 *= qs[lane + 32];
            const float* kp = &g_K[((size_t)(b*BN + j))*64];
            float z0 = y0 * kp[lane];
            float z1 = y1 * kp[lane + 32];
            z0 += __shfl_xor_sync(0xffffffffu, z0, 1);
            z0 += __shfl_xor_sync(0xffffffffu, z0, 2);
            z0 += __shfl_xor_sync(0xffffffffu, z0, 4);
            z1 += __shfl_xor_sync(0xffffffffu, z1, 1);
            z1 += __shfl_xor_sync(0xffffffffu, z1, 2);
            z1 += __shfl_xor_sync(0xffffffffu, z1, 4);
            if ((lane & 7) == 0) {
                int h0 = lane >> 3;  // heads 0..3 (z0), 4..7 (z1)
                g_scores[((size_t)(b*8 + h0    )*BN + i)*BN + j] = z0;
                g_scores[((size_t)(b*8 + h0 + 4)*BN + i)*BN + j] = z1;
            }
        }
    }
}
#define K2_SMEM (2*64*SMSB*2 + 64*SMSF*4)   // 18432 + 17408 = 35840

// ---------------- K3: global max per (b,h) ----------------
__global__ void __launch_bounds__(256) k3_max() {
    int bh = blockIdx.x >> 4, ch = blockIdx.x & 15;
    const float4* base = (const float4*)(g_scores + (size_t)bh*BN*BN + (size_t)ch*16384);
    float m = -INFINITY;
    for (int idx = threadIdx.x; idx < 4096; idx += 256) {
        float4 v = base[idx];
        m = fmaxf(m, fmaxf(fmaxf(v.x, v.y), fmaxf(v.z, v.w)));
    }
    #pragma unroll
    for (int off = 16; off; off >>= 1) m = fmaxf(m, __shfl_xor_sync(0xffffffffu, m, off));
    __shared__ float red[8];
    if ((threadIdx.x & 31) == 0) red[threadIdx.x >> 5] = m;
    __syncthreads();
    if (threadIdx.x < 8) {
        float mm = red[threadIdx.x];
        mm = fmaxf(mm, __shfl_xor_sync(0x000000ffu, mm, 4));
        mm = fmaxf(mm, __shfl_xor_sync(0x000000ffu, mm, 2));
        mm = fmaxf(mm, __shfl_xor_sync(0x000000ffu, mm, 1));
        if (threadIdx.x == 0) atomicMax(&g_maxbits[bh], f2key(mm));
    }
}

// ---------------- K4: exp/mask/k_RW + rowsum + att@V ----------------
__global__ void __launch_bounds__(256) k4_att(
    const float* __restrict__ kRW, const float* __restrict__ mask)
{
    extern __shared__ float Vs[];  // [64][513] : Vs[c*513 + j]
    int b  = blockIdx.y;
    int i0 = blockIdx.x * 8;
    int t = threadIdx.x, lane = t & 31, h = t >> 5;

    for (int idx = t; idx < BN*64; idx += 256) {
        int j = idx >> 6, c = idx & 63;
        Vs[c*513 + j] = g_V[((size_t)(b*BN + j))*64 + c];
    }
    __syncthreads();

    float mx = key2f(g_maxbits[b*8 + h]);

    for (int ii = 0; ii < 8; ++ii) {
        int i = i0 + ii;
        float mi = mask[b*BN + i];
        const float* sp = g_scores + ((size_t)(b*8 + h)*BN + i)*BN;
        const float* wp = kRW + ((size_t)(b*BN + i))*BN;
        float pden = 0.f;
        float pav[8];
        #pragma unroll
        for (int k = 0; k < 8; ++k) pav[k] = 0.f;

        for (int jt = 0; jt < 16; ++jt) {
            int j = jt*32 + lane;
            float pw = expf(sp[j] - mx) * wp[j] * mask[b*BN + j] * mi;
            pden += pw;
            #pragma unroll
            for (int k = 0; k < 8; ++k) pav[k] += pw * Vs[(h*8 + k)*513 + j];
        }
        #pragma unroll
        for (int off = 16; off; off >>= 1) {
            pden += __shfl_down_sync(0xffffffffu, pden, off);
            #pragma unroll
            for (int k = 0; k < 8; ++k) pav[k] += __shfl_down_sync(0xffffffffu, pav[k], off);
        }
        if (lane == 0) {
            float inv = 1.f / fmaxf(pden, 1e-6f);
            float4* op = (float4*)&g_hatt[((size_t)(b*BN + i))*64 + h*8];
            op[0] = make_float4(pav[0]*inv, pav[1]*inv, pav[2]*inv, pav[3]*inv);
            op[1] = make_float4(pav[4]*inv, pav[5]*inv, pav[6]*inv, pav[7]*inv);
        }
    }
}

// ---------------- K5: O-proj + residual + LN2 + FFN + residual ----------------
__global__ void __launch_bounds__(64) k5_out(
    const float* __restrict__ hin, const float* __restrict__ OW,
    const float* __restrict__ Ob, const float* __restrict__ g2,
    const float* __restrict__ b2, const float* __restrict__ Wf1,
    const float* __restrict__ bf1, const float* __restrict__ Wf2,
    const float* __restrict__ bf2, float* __restrict__ out)
{
    int row = blockIdx.x;
    int t = threadIdx.x;
    __shared__ float has[64], ys[64], hid[128];
    __shared__ float red[4];

    has[t] = g_hatt[row*64 + t];
    __syncthreads();

    float a = hin[row*64 + t] + Ob[t];
    #pragma unroll 8
    for (int d = 0; d < 64; ++d) a += has[d] * OW[d*64 + t];

    float s = a, sq = a*a;
    #pragma unroll
    for (int off = 16; off; off >>= 1) {
        s  += __shfl_down_sync(0xffffffffu, s,  off);
        sq += __shfl_down_sync(0xffffffffu, sq, off);
    }
    int wid = t >> 5, lane = t & 31;
    if (lane == 0) { red[wid*2] = s; red[wid*2+1] = sq; }
    __syncthreads();
    float S  = red[0] + red[2];
    float SQ = red[1] + red[3];
    float mean = S * (1.f/64.f);
    float var  = SQ * (1.f/64.f) - mean*mean;
    float rinv = rsqrtf(var + 1e-5f);
    ys[t] = (a - mean) * rinv * g2[t] + b2[t];
    __syncthreads();

    float h0 = bf1[t], h1 = bf1[t + 64];
    #pragma unroll 8
    for (int d = 0; d < 64; ++d) {
        float x = ys[d];
        h0 += x * Wf1[d*128 + t];
        h1 += x * Wf1[d*128 + t + 64];
    }
    hid[t]      = fmaxf(h0, 0.f);
    hid[t + 64] = fmaxf(h1, 0.f);
    __syncthreads();

    float o = a + bf2[t];
    #pragma unroll 8
    for (int c = 0; c < 128; ++c) o += hid[c] * Wf2[c*64 + t];
    out[row*64 + t] = o;
}

// ---------------- launch ----------------
extern "C" void kernel_launch(void* const* d_in, const int* in_sizes, int n_in,
                              void* d_out, int out_size)
{
    const float* h    = (const float*)d_in[0];
    const float* p    = (const float*)d_in[1];
    const float* e    = (const float*)d_in[2];
    const float* kRW  = (const float*)d_in[3];
    const float* mask = (const float*)d_in[4];
    const unsigned* adj = (const unsigned*)d_in[5];
    const float* WQ   = (const float*)d_in[6];
    const float* WK   = (const float*)d_in[7];
    const float* WV   = (const float*)d_in[8];
    const float* WQ2  = (const float*)d_in[9];
    const float* WK2  = (const float*)d_in[10];
    const float* WE   = (const float*)d_in[11];
    const float* WE2  = (const float*)d_in[12];
    const float* OW   = (const float*)d_in[13];
    const float* Ob   = (const float*)d_in[14];
    const float* g1   = (const float*)d_in[15];
    const float* b1   = (const float*)d_in[16];
    const float* g2   = (const float*)d_in[17];
    const float* b2   = (const float*)d_in[18];
    const float* Wf1  = (const float*)d_in[19];
    const float* bf1  = (const float*)d_in[20];
    const float* Wf2  = (const float*)d_in[21];
    const float* bf2  = (const float*)d_in[22];
    float* out = (float*)d_out;

    cudaFuncSetAttribute(k2_scores, cudaFuncAttributeMaxDynamicSharedMemorySize, K2_SMEM);
    cudaFuncSetAttribute(k4_att, cudaFuncAttributeMaxDynamicSharedMemorySize, 64*513*4);

    k0_init<<<1, 256>>>(WE2);
    k1_proj<<<NROWS, 64>>>(h, p, g1, b1, WQ, WK, WV, WQ2, WK2);
    k2_scores<<<NROWS, 128, K2_SMEM>>>(e, adj, WE);
    k3_max<<<BH*16, 256>>>();
    k4_att<<<dim3(64, BB), 256, 64*513*4>>>(kRW, mask);
    k5_out<<<NROWS, 64>>>(h, OW, Ob, g2, b2, Wf1, bf1, Wf2, bf2, out);
}